// round 14
// baseline (speedup 1.0000x reference)
#include <cuda_runtime.h>

#define BB   16
#define TT   4096
#define FEAT 256
#define KW   5
#define CH   64            // seq_scan chunk (steps)
#define QS   1024          // steps per scan part
#define NQ   4             // number of parts

// Scratch (no allocations allowed).
__device__ float  g_weff[FEAT * KW];
__device__ float  g_bias;
__device__ float  g_p[BB * TT * KW];
__device__ float  g_alphas[BB * TT];      // [b][t]
__device__ float  g_alphasT[TT * BB];     // [t][b] for scan staging
__device__ float4 g_accq4[(TT / 4) * BB]; // acc BEFORE step, [(t>>2)*16+b]
__device__ float  g_accsave[BB];          // scan carry between parts
__device__ int    g_ft[BB * TT];          // fire times (global rank order)
__device__ int2   g_seg[BB * TT];
__device__ int    g_qcnt[NQ + 1][BB];     // cumulative fire counts per part

#define ACCB(t, b) (((const float*)g_accq4)[(((t) >> 2) * BB + (b)) * 4 + ((t) & 3)])

// ---------------------------------------------------------------------------
// Kernel 1: fold lin_w into conv_w
// ---------------------------------------------------------------------------
__global__ void fold_kernel(const float* __restrict__ conv_w,
                            const float* __restrict__ conv_b,
                            const float* __restrict__ lin_w,
                            const float* __restrict__ lin_b) {
    int j = blockIdx.x * blockDim.x + threadIdx.x;
    if (j < FEAT * KW) {
        float s = 0.f;
#pragma unroll 4
        for (int o = 0; o < FEAT; ++o)
            s = fmaf(lin_w[o], conv_w[o * (FEAT * KW) + j], s);
        g_weff[j] = s;
    }
    if (blockIdx.x == 0) {
        __shared__ float sh[256];
        sh[threadIdx.x] = conv_b[threadIdx.x] * lin_w[threadIdx.x];
        __syncthreads();
        for (int ofs = 128; ofs > 0; ofs >>= 1) {
            if ((int)threadIdx.x < ofs) sh[threadIdx.x] += sh[threadIdx.x + ofs];
            __syncthreads();
        }
        if (threadIdx.x == 0) g_bias = sh[0] + lin_b[0];
    }
}

// ---------------------------------------------------------------------------
// Kernel 2: p[row][k] = dot(x[row,:], w_eff[:,k])
// ---------------------------------------------------------------------------
__global__ __launch_bounds__(256) void pk_kernel(const float* __restrict__ x) {
    int warp_global = (blockIdx.x * blockDim.x + threadIdx.x) >> 5;
    int lane = threadIdx.x & 31;
    int c0 = lane * 4;

    float w[8][KW];
#pragma unroll
    for (int j = 0; j < 8; ++j) {
        int c = (j < 4) ? (c0 + j) : (c0 + 124 + j);
#pragma unroll
        for (int k = 0; k < KW; ++k) w[j][k] = g_weff[c * KW + k];
    }

    long row0 = (long)warp_global * 8;
    for (int r = 0; r < 8; ++r) {
        long row = row0 + r;
        const float4* r4 = (const float4*)(x + row * FEAT);
        float4 va = r4[lane];
        float4 vb = r4[lane + 32];
        float xs[8] = {va.x, va.y, va.z, va.w, vb.x, vb.y, vb.z, vb.w};
        float s[KW] = {0.f, 0.f, 0.f, 0.f, 0.f};
#pragma unroll
        for (int j = 0; j < 8; ++j)
#pragma unroll
            for (int k = 0; k < KW; ++k)
                s[k] = fmaf(xs[j], w[j][k], s[k]);
#pragma unroll
        for (int k = 0; k < KW; ++k)
#pragma unroll
            for (int ofs = 16; ofs > 0; ofs >>= 1)
                s[k] += __shfl_xor_sync(0xffffffffu, s[k], ofs);
        if (lane == 0) {
#pragma unroll
            for (int k = 0; k < KW; ++k) g_p[row * KW + k] = s[k];
        }
    }
}

// ---------------------------------------------------------------------------
// Kernel 3: alphas = sigmoid(bias + sum_k p[t+k-2, k]), dual layout.
// ---------------------------------------------------------------------------
__global__ void alpha_kernel() {
    int i = blockIdx.x * blockDim.x + threadIdx.x;
    if (i >= BB * TT) return;
    int t = i & (TT - 1);
    int b = i >> 12;
    float s = g_bias;
#pragma unroll
    for (int k = 0; k < KW; ++k) {
        int tt = t + k - 2;
        if (tt >= 0 && tt < TT) s += g_p[(long)(i + k - 2) * KW + k];
    }
    float v = 1.f / (1.f + expf(-s));
    g_alphas[i] = v;
    g_alphasT[t * BB + b] = v;
}

// ---------------------------------------------------------------------------
// Kernel 4: scan part q — 1024 steps, acc carried via g_accsave. Same fp ops
// and accq stores as R11's scan, just windowed.
// ---------------------------------------------------------------------------
__global__ __launch_bounds__(32, 1) void scan_part_kernel(int q) {
    __shared__ float sa[2][CH * BB];
    const int lane = threadIdx.x;
    const int b = lane & 15;

    const float4* src = ((const float4*)g_alphasT) + (size_t)q * (QS * BB / 4);

    {
        float4 v[8];
#pragma unroll
        for (int i = 0; i < 8; ++i) v[i] = src[lane + 32 * i];
#pragma unroll
        for (int i = 0; i < 8; ++i) ((float4*)sa[0])[lane + 32 * i] = v[i];
    }
    __syncwarp();

    float acc = (q == 0) ? 0.f : g_accsave[b];
    int buf = 0;
    float4* accq = g_accq4;
    const int NCH = QS / CH;                    // 16 chunks per part

    for (int c = 0; c < NCH; ++c) {
        float4 pf[8];
        if (c + 1 < NCH) {
            const float4* s2 = src + (c + 1) * (CH * BB / 4);
#pragma unroll
            for (int i = 0; i < 8; ++i) pf[i] = s2[lane + 32 * i];
        }

        if (lane < 16) {
            const float* s = sa[buf] + b;
            float cur[16], nxt[16];
#pragma unroll
            for (int j = 0; j < 16; ++j) cur[j] = s[j * BB];
#pragma unroll
            for (int sub = 0; sub < CH / 16; ++sub) {
                if (sub + 1 < CH / 16) {
#pragma unroll
                    for (int j = 0; j < 16; ++j)
                        nxt[j] = s[(sub * 16 + 16 + j) * BB];
                }
                int qbase = (q * QS + c * CH + sub * 16) >> 2;
#pragma unroll
                for (int g4 = 0; g4 < 4; ++g4) {
                    float4 av;
#pragma unroll
                    for (int j = 0; j < 4; ++j) {
                        float a = cur[g4 * 4 + j];
                        ((float*)&av)[j] = acc;
                        float acc_new = acc + a;
                        float a1 = 1.0f - acc;
                        float a2 = a - a1;
                        acc = (acc_new >= 1.0f) ? a2 : acc_new;
                    }
                    accq[(qbase + g4) * BB + b] = av;
                }
#pragma unroll
                for (int j = 0; j < 16; ++j) cur[j] = nxt[j];
            }
        }

        if (c + 1 < NCH) {
            buf ^= 1;
            __syncwarp();
#pragma unroll
            for (int i = 0; i < 8; ++i)
                ((float4*)sa[buf])[lane + 32 * i] = pf[i];
            __syncwarp();
        }
    }
    if (lane < 16) g_accsave[b] = acc;
}

// ---------------------------------------------------------------------------
// Kernel 5: compact part q. Rebuild fires for steps [q*1024,(q+1)*1024) with
// the identical fp compare, rank them globally (offset by g_qcnt[q]), write
// g_ft + g_seg for segments ending in this quarter, publish g_qcnt[q+1].
// ---------------------------------------------------------------------------
__global__ __launch_bounds__(256) void compact_part_kernel(int q) {
    int b = blockIdx.x;
    int t = threadIdx.x;                      // owns 4 steps
    __shared__ int tmp[256];

    int base = q * QS + t * 4;
    unsigned m = 0u;
    {
        const float4 av = g_accq4[(size_t)(base >> 2) * BB + b];
        const float4 al = *(const float4*)(g_alphas + (size_t)b * TT + base);
        const float accs[4] = {av.x, av.y, av.z, av.w};
        const float as[4]   = {al.x, al.y, al.z, al.w};
#pragma unroll
        for (int j = 0; j < 4; ++j)
            if (accs[j] + as[j] >= 1.0f) m |= (1u << j);
    }
    int cnt = __popc(m);

    tmp[t] = cnt;
    __syncthreads();
    for (int ofs = 1; ofs < 256; ofs <<= 1) {
        int v = (t >= ofs) ? tmp[t - ofs] : 0;
        __syncthreads();
        tmp[t] += v;
        __syncthreads();
    }
    int cnt_in = g_qcnt[q][b];
    int total = tmp[255];
    int rank = cnt_in + tmp[t] - cnt;         // exclusive + carry
    const int wbase = b * TT;

    unsigned mm = m;
    while (mm) {
        int i = __ffs(mm) - 1;
        mm &= mm - 1;
        g_ft[wbase + rank] = base + i;
        ++rank;
    }
    __syncthreads();

    int cnt_out = cnt_in + total;
    for (int j = cnt_in + t; j < cnt_out; j += 256) {
        int s = (j == 0) ? -1 : g_ft[wbase + j - 1];
        g_seg[wbase + j] = make_int2(s, g_ft[wbase + j]);
    }
    if (t == 0) g_qcnt[q + 1][b] = cnt_out;
}

// ---------------------------------------------------------------------------
// Kernel 6: emit part q — rows [g_qcnt[q], g_qcnt[q+1]). Tail rows stay zero
// from the upfront memset. fp ops identical to R11.
// ---------------------------------------------------------------------------
__global__ __launch_bounds__(FEAT) void emit_part_kernel(const float* __restrict__ x,
                                                         float* __restrict__ out,
                                                         int q) {
    int b = blockIdx.x;
    int d = threadIdx.x;
    int j0 = g_qcnt[q][b];
    int j1 = g_qcnt[q + 1][b];
    const float* xb = x + (size_t)b * TT * FEAT;
    const float* ab = g_alphas + (size_t)b * TT;
    const int wbase = b * TT;
    float* ob = out + (size_t)b * TT * FEAT;
    const int stride = gridDim.y;

    int j = j0 + blockIdx.y;
    int2 se = (j < j1) ? g_seg[wbase + j] : make_int2(0, 0);

    while (j < j1) {
        int jn = j + stride;
        int2 se_nxt = (jn < j1) ? g_seg[wbase + jn] : make_int2(0, 0);

        float accv = 0.f;
        int u0 = 0;
        if (se.x >= 0) {
            float a2 = ab[se.x] - (1.0f - ACCB(se.x, b));
            accv = a2 * xb[(size_t)se.x * FEAT + d];
            u0 = se.x + 1;
        }
        for (int u = u0; u < se.y; ++u)
            accv = fmaf(ab[u], xb[(size_t)u * FEAT + d], accv);
        float we = 1.0f - ACCB(se.y, b);
        accv = fmaf(we, xb[(size_t)se.y * FEAT + d], accv);
        ob[(size_t)j * FEAT + d] = accv;

        se = se_nxt;
        j = jn;
    }
}

// ---------------------------------------------------------------------------
// Kernel 7: finalize — lens + n==0 fallback (emit final hacc as row 0).
// ---------------------------------------------------------------------------
__global__ __launch_bounds__(FEAT) void fin_kernel(const float* __restrict__ x,
                                                   float* __restrict__ out,
                                                   float* __restrict__ lens,
                                                   int write_len) {
    int b = blockIdx.x;
    int d = threadIdx.x;
    int n = g_qcnt[NQ][b];
    if (n == 0) {
        const float* xb = x + (size_t)b * TT * FEAT;
        const float* ab = g_alphas + (size_t)b * TT;
        float accv = 0.f;
        for (int u = 0; u < TT; ++u)
            accv = fmaf(ab[u], xb[(size_t)u * FEAT + d], accv);
        out[(size_t)b * TT * FEAT + d] = accv;
        n = 1;
    }
    if (write_len && d == 0) lens[b] = (float)n;
}

// ---------------------------------------------------------------------------
extern "C" void kernel_launch(void* const* d_in, const int* in_sizes, int n_in,
                              void* d_out, int out_size) {
    const float* x      = (const float*)d_in[0];
    const float* conv_w = (const float*)d_in[1];
    const float* conv_b = (const float*)d_in[2];
    const float* lin_w  = (const float*)d_in[3];
    const float* lin_b  = (const float*)d_in[4];
    float* out = (float*)d_out;

    cudaStream_t s2;
    cudaStreamCreateWithFlags(&s2, cudaStreamNonBlocking);
    cudaEvent_t eFork, eScan[NQ], eSide;
    cudaEventCreateWithFlags(&eFork, cudaEventDisableTiming);
    for (int q = 0; q < NQ; ++q)
        cudaEventCreateWithFlags(&eScan[q], cudaEventDisableTiming);
    cudaEventCreateWithFlags(&eSide, cudaEventDisableTiming);

    // Side branch: zero entire output up-front (overlaps fold/pk/alpha).
    cudaEventRecord(eFork, 0);
    cudaStreamWaitEvent(s2, eFork, 0);
    cudaMemsetAsync(d_out, 0, (size_t)out_size * sizeof(float), s2);

    // Main chain.
    fold_kernel<<<5, 256>>>(conv_w, conv_b, lin_w, lin_b);
    pk_kernel<<<1024, 256>>>(x);
    alpha_kernel<<<(BB * TT + 255) / 256, 256>>>();
    for (int q = 0; q < NQ; ++q) {
        scan_part_kernel<<<1, 32>>>(q);
        cudaEventRecord(eScan[q], 0);
    }

    // Side pipeline: compact+emit per quarter, overlapped with later scan parts.
    const size_t dense = (size_t)BB * TT * FEAT;
    int write_len = (out_size >= (int)(dense + BB)) ? 1 : 0;
    float* lens = out + dense;
    for (int q = 0; q < NQ; ++q) {
        cudaStreamWaitEvent(s2, eScan[q], 0);
        compact_part_kernel<<<BB, 256, 0, s2>>>(q);
        emit_part_kernel<<<dim3(BB, 256), FEAT, 0, s2>>>(x, out, q);
    }
    fin_kernel<<<BB, FEAT, 0, s2>>>(x, out, lens, write_len);
    cudaEventRecord(eSide, s2);
    cudaStreamWaitEvent(0, eSide, 0);

    cudaEventDestroy(eFork);
    for (int q = 0; q < NQ; ++q) cudaEventDestroy(eScan[q]);
    cudaEventDestroy(eSide);
    cudaStreamDestroy(s2);
}

// round 16
// speedup vs baseline: 1.0302x; 1.0302x over previous
#include <cuda_runtime.h>

#define BB   16
#define TT   4096
#define FEAT 256
#define KW   5
#define CH   64            // seq_scan chunk (steps)

// Scratch (no allocations allowed).
__device__ float  g_weff[FEAT * KW];
__device__ float  g_bias;
__device__ float  g_p[BB * TT * KW];
__device__ float  g_alphas[BB * TT];     // [b][t] for emit/compact
__device__ float  g_alphasT[TT * BB];    // [t][b] for seq_scan (coalesced)
__device__ float4 g_accq4[(TT / 4) * BB]; // acc BEFORE step, [(t>>2)*16+b]
__device__ int    g_ft[BB * TT];
__device__ int2   g_seg[BB * TT];
__device__ int    g_n[BB];
__device__ int    g_nofire[BB];

#define ACCB(t, b) (((const float*)g_accq4)[(((t) >> 2) * BB + (b)) * 4 + ((t) & 3)])

// ---------------------------------------------------------------------------
// Kernel 1: fold lin_w into conv_w  ->  w_eff[c,k] = sum_o lin_w[o]*conv_w[o,c,k]
// ---------------------------------------------------------------------------
__global__ void fold_kernel(const float* __restrict__ conv_w,
                            const float* __restrict__ conv_b,
                            const float* __restrict__ lin_w,
                            const float* __restrict__ lin_b) {
    int j = blockIdx.x * blockDim.x + threadIdx.x;
    if (j < FEAT * KW) {
        float s = 0.f;
#pragma unroll 4
        for (int o = 0; o < FEAT; ++o)
            s = fmaf(lin_w[o], conv_w[o * (FEAT * KW) + j], s);
        g_weff[j] = s;
    }
    if (blockIdx.x == 0) {
        __shared__ float sh[256];
        sh[threadIdx.x] = conv_b[threadIdx.x] * lin_w[threadIdx.x];
        __syncthreads();
        for (int ofs = 128; ofs > 0; ofs >>= 1) {
            if ((int)threadIdx.x < ofs) sh[threadIdx.x] += sh[threadIdx.x + ofs];
            __syncthreads();
        }
        if (threadIdx.x == 0) g_bias = sh[0] + lin_b[0];
    }
}

// ---------------------------------------------------------------------------
// Kernel 2: p[row][k] = dot(x[row,:], w_eff[:,k]) for k=0..4.
// ---------------------------------------------------------------------------
__global__ __launch_bounds__(256) void pk_kernel(const float* __restrict__ x) {
    int warp_global = (blockIdx.x * blockDim.x + threadIdx.x) >> 5;
    int lane = threadIdx.x & 31;
    int c0 = lane * 4;

    float w[8][KW];
#pragma unroll
    for (int j = 0; j < 8; ++j) {
        int c = (j < 4) ? (c0 + j) : (c0 + 124 + j);
#pragma unroll
        for (int k = 0; k < KW; ++k) w[j][k] = g_weff[c * KW + k];
    }

    long row0 = (long)warp_global * 8;
    for (int r = 0; r < 8; ++r) {
        long row = row0 + r;
        const float4* r4 = (const float4*)(x + row * FEAT);
        float4 va = r4[lane];
        float4 vb = r4[lane + 32];
        float xs[8] = {va.x, va.y, va.z, va.w, vb.x, vb.y, vb.z, vb.w};
        float s[KW] = {0.f, 0.f, 0.f, 0.f, 0.f};
#pragma unroll
        for (int j = 0; j < 8; ++j)
#pragma unroll
            for (int k = 0; k < KW; ++k)
                s[k] = fmaf(xs[j], w[j][k], s[k]);
#pragma unroll
        for (int k = 0; k < KW; ++k)
#pragma unroll
            for (int ofs = 16; ofs > 0; ofs >>= 1)
                s[k] += __shfl_xor_sync(0xffffffffu, s[k], ofs);
        if (lane == 0) {
#pragma unroll
            for (int k = 0; k < KW; ++k) g_p[row * KW + k] = s[k];
        }
    }
}

// ---------------------------------------------------------------------------
// Kernel 3: alphas[b,t] = sigmoid( bias + sum_k p[b, t+k-2, k] ), dual layout.
// ---------------------------------------------------------------------------
__global__ void alpha_kernel() {
    int i = blockIdx.x * blockDim.x + threadIdx.x;
    if (i >= BB * TT) return;
    int t = i & (TT - 1);
    int b = i >> 12;
    float s = g_bias;
#pragma unroll
    for (int k = 0; k < KW; ++k) {
        int tt = t + k - 2;
        if (tt >= 0 && tt < TT) s += g_p[(long)(i + k - 2) * KW + k];
    }
    float v = 1.f / (1.f + expf(-s));
    g_alphas[i] = v;
    g_alphasT[t * BB + b] = v;
}

// ---------------------------------------------------------------------------
// Kernel 4: sequential alpha scan — R11 structure, single change: the select
// is forced to SETP(pred-as-data)+SELP via inline PTX so the chain is
// FADD(4)->FSETP(4)->SELP(4)=12 cyc instead of the @P-guarded-MOV 21+ path.
// fp semantics identical (same compare, same selected values).
// ---------------------------------------------------------------------------
__global__ __launch_bounds__(32, 1) void seq_scan_kernel() {
    __shared__ float sa[2][CH * BB];          // 2 x 4KB
    const int lane = threadIdx.x;
    const int b = lane & 15;

    const float4* src = (const float4*)g_alphasT;

    {
        float4 v[8];
#pragma unroll
        for (int i = 0; i < 8; ++i) v[i] = src[lane + 32 * i];
#pragma unroll
        for (int i = 0; i < 8; ++i) ((float4*)sa[0])[lane + 32 * i] = v[i];
    }
    __syncwarp();

    float acc = 0.f;
    int buf = 0;
    float4* accq = g_accq4;

    for (int c = 0; c < TT / CH; ++c) {
        float4 pf[8];
        if (c + 1 < TT / CH) {
            const float4* s2 = src + (c + 1) * (CH * BB / 4);
#pragma unroll
            for (int i = 0; i < 8; ++i) pf[i] = s2[lane + 32 * i];
        }

        if (lane < 16) {
            const float* s = sa[buf] + b;
            float cur[16], nxt[16];
#pragma unroll
            for (int j = 0; j < 16; ++j) cur[j] = s[j * BB];
#pragma unroll
            for (int sub = 0; sub < CH / 16; ++sub) {
                if (sub + 1 < CH / 16) {
#pragma unroll
                    for (int j = 0; j < 16; ++j)
                        nxt[j] = s[(sub * 16 + 16 + j) * BB];
                }
                int qbase = (c * CH + sub * 16) >> 2;
#pragma unroll
                for (int q = 0; q < 4; ++q) {
                    float4 av;
#pragma unroll
                    for (int j = 0; j < 4; ++j) {
                        float a = cur[q * 4 + j];
                        ((float*)&av)[j] = acc;
                        float acc_new = acc + a;
                        float a1 = 1.0f - acc;
                        float a2 = a - a1;
                        // acc = (acc_new >= 1.0f) ? a2 : acc_new;  -- forced SELP
                        asm("{\n\t"
                            ".reg .pred p;\n\t"
                            "setp.ge.f32 p, %1, 0f3F800000;\n\t"
                            "selp.f32 %0, %2, %1, p;\n\t"
                            "}"
                            : "=f"(acc) : "f"(acc_new), "f"(a2));
                    }
                    accq[(qbase + q) * BB + b] = av;
                }
#pragma unroll
                for (int j = 0; j < 16; ++j) cur[j] = nxt[j];
            }
        }

        if (c + 1 < TT / CH) {
            buf ^= 1;
            __syncwarp();
#pragma unroll
            for (int i = 0; i < 8; ++i)
                ((float4*)sa[buf])[lane + 32 * i] = pf[i];
            __syncwarp();
        }
    }
}

// ---------------------------------------------------------------------------
// Kernel 5: compaction. Recomputes fire = (acc_before + alpha >= 1) with the
// exact fp32 op the scan used, then prefix + scatter -> segment table.
// ---------------------------------------------------------------------------
__global__ __launch_bounds__(128) void compact_kernel(float* __restrict__ lens,
                                                      int write_len) {
    int b = blockIdx.x;
    int t = threadIdx.x;
    __shared__ int pre[129];
    __shared__ int tmp[128];

    unsigned m = 0u;
    {
        int base = t * 32;
        const float* ab = g_alphas + (size_t)b * TT + base;
        const float4* aq = g_accq4 + (base >> 2) * BB + b;
#pragma unroll
        for (int qq = 0; qq < 8; ++qq) {
            float4 v = aq[qq * BB];
            float accs[4] = {v.x, v.y, v.z, v.w};
#pragma unroll
            for (int j = 0; j < 4; ++j) {
                int i = qq * 4 + j;
                if (accs[j] + ab[i] >= 1.0f) m |= (1u << i);
            }
        }
    }
    int cnt = __popc(m);

    tmp[t] = cnt;
    __syncthreads();
    for (int ofs = 1; ofs < 128; ofs <<= 1) {
        int v = (t >= ofs) ? tmp[t - ofs] : 0;
        __syncthreads();
        tmp[t] += v;
        __syncthreads();
    }
    pre[t + 1] = tmp[t];
    if (t == 0) pre[0] = 0;
    __syncthreads();

    int n = pre[128];
    const int wbase = b * TT;

    int rank = pre[t];
    unsigned mm = m;
    while (mm) {
        int i = __ffs(mm) - 1;
        mm &= mm - 1;
        g_ft[wbase + rank] = t * 32 + i;
        ++rank;
    }
    __syncthreads();

    if (n == 0) {
        if (t == 0) {
            g_ft[wbase] = TT - 1;
            g_seg[wbase] = make_int2(-1, TT - 1);
            g_n[b] = 1;
            g_nofire[b] = 1;
            if (write_len) lens[b] = 1.0f;
        }
        return;
    }

    for (int j = t; j < n; j += 128) {
        int s = (j == 0) ? -1 : g_ft[wbase + j - 1];
        g_seg[wbase + j] = make_int2(s, g_ft[wbase + j]);
    }
    if (t == 0) {
        g_n[b] = n;
        g_nofire[b] = 0;
        if (write_len) lens[b] = (float)n;
    }
}

// ---------------------------------------------------------------------------
// Kernel 6: fused emission + tail zero (R11's measured-best config:
// gridDim.y=1024, pipelined descriptors).
// ---------------------------------------------------------------------------
__global__ __launch_bounds__(FEAT) void emit_kernel(const float* __restrict__ x,
                                                    float* __restrict__ out) {
    int b = blockIdx.x;
    int d = threadIdx.x;
    int n = g_n[b];
    int nofire = g_nofire[b];
    const float* xb = x + (size_t)b * TT * FEAT;
    const float* ab = g_alphas + (size_t)b * TT;
    const int wbase = b * TT;
    float* ob = out + (size_t)b * TT * FEAT;
    const int stride = gridDim.y;

    int j = blockIdx.y;
    int2 se = (j < n) ? g_seg[wbase + j] : make_int2(0, 0);

    for (; j < TT; ) {
        int jn = j + stride;
        if (j >= n) {
            ob[(size_t)j * FEAT + d] = 0.f;
            j = jn;
            continue;
        }
        int2 se_nxt = (jn < n) ? g_seg[wbase + jn] : make_int2(0, 0);

        float accv = 0.f;
        int u0 = 0;
        if (se.x >= 0) {
            float a2 = ab[se.x] - (1.0f - ACCB(se.x, b));
            accv = a2 * xb[(size_t)se.x * FEAT + d];
            u0 = se.x + 1;
        }
        for (int u = u0; u < se.y; ++u)
            accv = fmaf(ab[u], xb[(size_t)u * FEAT + d], accv);
        float we = nofire ? ab[se.y] : (1.0f - ACCB(se.y, b));
        accv = fmaf(we, xb[(size_t)se.y * FEAT + d], accv);
        ob[(size_t)j * FEAT + d] = accv;

        se = se_nxt;
        j = jn;
    }
}

// ---------------------------------------------------------------------------
extern "C" void kernel_launch(void* const* d_in, const int* in_sizes, int n_in,
                              void* d_out, int out_size) {
    const float* x      = (const float*)d_in[0];
    const float* conv_w = (const float*)d_in[1];
    const float* conv_b = (const float*)d_in[2];
    const float* lin_w  = (const float*)d_in[3];
    const float* lin_b  = (const float*)d_in[4];
    float* out = (float*)d_out;

    const size_t dense = (size_t)BB * TT * FEAT;
    if ((size_t)out_size > dense)
        cudaMemsetAsync(out + dense, 0, ((size_t)out_size - dense) * sizeof(float), 0);

    fold_kernel<<<5, 256>>>(conv_w, conv_b, lin_w, lin_b);
    pk_kernel<<<1024, 256>>>(x);
    alpha_kernel<<<(BB * TT + 255) / 256, 256>>>();

    seq_scan_kernel<<<1, 32>>>();

    int write_len = (out_size >= (int)(dense + BB)) ? 1 : 0;
    float* lens = out + dense;
    compact_kernel<<<BB, 128>>>(lens, write_len);

    emit_kernel<<<dim3(BB, 1024), FEAT>>>(x, out);
}